// round 6
// baseline (speedup 1.0000x reference)
#include <cuda_runtime.h>

// Maxwell RNN: per-row linear recurrence. One block = one full row
// (8192 = 512 threads x 16 elems). No inter-block dependency.
//
//   gamma_t = (1 - 0.5*dt_t)*gamma_{t-1} + 0.5*dt_t*eps_t,  gamma_{-1} = 0
//   sig_t   = 2.5*eps_t - gamma_{t-1}
//
// During the local affine fold we keep, per element, the affine form of the
// OUTPUT in the thread-start state g:  sig_j = C_j - Pp_j * g,
// with C_j = 2.5*e_j - Qp_j (prefix before step j). C/Pp overwrite ee/dd
// in place, so the final fixup is 16 independent FMAs (no serial replay).

constexpr int Bn  = 4096;
constexpr int Tn  = 8192;
constexpr int TPB = 512;
constexpr int EPT = 16;
constexpr int NW  = TPB / 32;           // 16 warps
static_assert(TPB * EPT == Tn, "one block = one row");

__global__ void __launch_bounds__(TPB, 3)
maxwell_row_kernel(const float* __restrict__ eps, const float* __restrict__ dt,
                   float* __restrict__ out) {
    __shared__ float sWP[NW];
    __shared__ float sWQ[NW];

    const int tid  = threadIdx.x;
    const int lane = tid & 31;
    const int wid  = tid >> 5;

    const size_t base = (size_t)blockIdx.x * Tn + (size_t)tid * EPT;

    // ---- load 16 eps + 16 dt as 8 independent float4s ----
    float ee[EPT], dd[EPT];
    #pragma unroll
    for (int v = 0; v < 4; v++) {
        float4 e4 = *reinterpret_cast<const float4*>(eps + base + v * 4);
        float4 d4 = *reinterpret_cast<const float4*>(dt  + base + v * 4);
        ee[v*4+0] = e4.x; ee[v*4+1] = e4.y; ee[v*4+2] = e4.z; ee[v*4+3] = e4.w;
        dd[v*4+0] = d4.x; dd[v*4+1] = d4.y; dd[v*4+2] = d4.z; dd[v*4+3] = d4.w;
    }

    // ---- local affine fold; rewrite (ee,dd) -> (C, Pp) in place ----
    float P = 1.0f, Q = 0.0f;
    #pragma unroll
    for (int j = 0; j < EPT; j++) {
        float e = ee[j];
        float d = dd[j];
        dd[j] = P;                      // Pp_j
        ee[j] = fmaf(2.5f, e, -Q);      // C_j
        float ad = 0.5f * d;
        float A  = 1.0f - ad;
        Q = fmaf(A, Q, ad * e);
        P = P * A;
    }

    // ---- warp-inclusive affine scan (5 shuffle steps) ----
    #pragma unroll
    for (int off = 1; off < 32; off <<= 1) {
        float Pu = __shfl_up_sync(0xFFFFFFFFu, P, off);
        float Qu = __shfl_up_sync(0xFFFFFFFFu, Q, off);
        if (lane >= off) { Q = fmaf(P, Qu, Q); P *= Pu; }
    }
    // thread-exclusive prefix within warp
    float LPe = __shfl_up_sync(0xFFFFFFFFu, P, 1);
    float LQe = __shfl_up_sync(0xFFFFFFFFu, Q, 1);
    if (lane == 0) { LPe = 1.0f; LQe = 0.0f; }

    if (lane == 31) { sWP[wid] = P; sWQ[wid] = Q; }
    __syncthreads();

    // ---- redundant cross-warp scan in EVERY warp (no 2nd barrier) ----
    float p = (lane < NW) ? sWP[lane] : 1.0f;
    float q = (lane < NW) ? sWQ[lane] : 0.0f;
    #pragma unroll
    for (int off = 1; off < NW; off <<= 1) {
        float pu = __shfl_up_sync(0xFFFFFFFFu, p, off);
        float qu = __shfl_up_sync(0xFFFFFFFFu, q, off);
        if (lane >= off) { q = fmaf(p, qu, q); p *= pu; }
    }
    // block-start gamma = 0, so warp-start gamma = inclusive Q at wid-1.
    float gw = (wid == 0) ? 0.0f : __shfl_sync(0xFFFFFFFFu, q, wid - 1);
    float gt = fmaf(LPe, gw, LQe);      // thread-start gamma

    // ---- fixup (independent FMAs) + coalesced float4 stores ----
    #pragma unroll
    for (int v = 0; v < 4; v++) {
        float4 o;
        o.x = fmaf(-dd[v*4+0], gt, ee[v*4+0]);
        o.y = fmaf(-dd[v*4+1], gt, ee[v*4+1]);
        o.z = fmaf(-dd[v*4+2], gt, ee[v*4+2]);
        o.w = fmaf(-dd[v*4+3], gt, ee[v*4+3]);
        *reinterpret_cast<float4*>(out + base + v * 4) = o;
    }
}

extern "C" void kernel_launch(void* const* d_in, const int* in_sizes, int n_in,
                              void* d_out, int out_size) {
    const float* eps = (const float*)d_in[0];
    const float* dt  = (const float*)d_in[1];
    float* out = (float*)d_out;

    maxwell_row_kernel<<<Bn, TPB>>>(eps, dt, out);
}

// round 7
// speedup vs baseline: 1.1449x; 1.1449x over previous
#include <cuda_runtime.h>

// Maxwell RNN: per-row linear recurrence. One block = one full row
// (8192 = 512 threads x 16 elems). No inter-block dependency.
//
//   gamma_t = (1 - 0.5*dt_t)*gamma_{t-1} + 0.5*dt_t*eps_t,  gamma_{-1} = 0
//   sig_t   = 2.5*eps_t - gamma_{t-1}
//
// sig is affine in the thread-start state g: sig_j = C_j - Pp_j * g with
// C_j = 2.5*e_j - Qp_j. C/Pp overwrite ee/dd in place, so the fixup is 16
// independent FMAs (no serial replay). NO register cap: per-thread MLP
// (8 batched LDG.128) is the binding resource, not occupancy (R6 lesson).

constexpr int Bn  = 4096;
constexpr int Tn  = 8192;
constexpr int TPB = 512;
constexpr int EPT = 16;
constexpr int NW  = TPB / 32;           // 16 warps
static_assert(TPB * EPT == Tn, "one block = one row");

__global__ void __launch_bounds__(TPB)
maxwell_row_kernel(const float* __restrict__ eps, const float* __restrict__ dt,
                   float* __restrict__ out) {
    __shared__ float sWP[NW];
    __shared__ float sWQ[NW];

    const int tid  = threadIdx.x;
    const int lane = tid & 31;
    const int wid  = tid >> 5;

    const size_t base = (size_t)blockIdx.x * Tn + (size_t)tid * EPT;
    const float4* __restrict__ pe = reinterpret_cast<const float4*>(eps + base);
    const float4* __restrict__ pd = reinterpret_cast<const float4*>(dt  + base);

    // ---- 8 independent float4 loads, batched up front (max MLP) ----
    float4 ev[4], dv[4];
    #pragma unroll
    for (int v = 0; v < 4; v++) ev[v] = pe[v];
    #pragma unroll
    for (int v = 0; v < 4; v++) dv[v] = pd[v];

    float ee[EPT], dd[EPT];
    #pragma unroll
    for (int v = 0; v < 4; v++) {
        ee[v*4+0] = ev[v].x; ee[v*4+1] = ev[v].y; ee[v*4+2] = ev[v].z; ee[v*4+3] = ev[v].w;
        dd[v*4+0] = dv[v].x; dd[v*4+1] = dv[v].y; dd[v*4+2] = dv[v].z; dd[v*4+3] = dv[v].w;
    }

    // ---- local affine fold; rewrite (ee,dd) -> (C, Pp) in place ----
    float P = 1.0f, Q = 0.0f;
    #pragma unroll
    for (int j = 0; j < EPT; j++) {
        float e = ee[j];
        float d = dd[j];
        dd[j] = P;                      // Pp_j
        ee[j] = fmaf(2.5f, e, -Q);      // C_j
        float ad = 0.5f * d;
        float A  = 1.0f - ad;
        Q = fmaf(A, Q, ad * e);
        P = P * A;
    }

    // ---- warp-inclusive affine scan (5 shuffle steps) ----
    #pragma unroll
    for (int off = 1; off < 32; off <<= 1) {
        float Pu = __shfl_up_sync(0xFFFFFFFFu, P, off);
        float Qu = __shfl_up_sync(0xFFFFFFFFu, Q, off);
        if (lane >= off) { Q = fmaf(P, Qu, Q); P *= Pu; }
    }
    // thread-exclusive prefix within warp
    float LPe = __shfl_up_sync(0xFFFFFFFFu, P, 1);
    float LQe = __shfl_up_sync(0xFFFFFFFFu, Q, 1);
    if (lane == 0) { LPe = 1.0f; LQe = 0.0f; }

    if (lane == 31) { sWP[wid] = P; sWQ[wid] = Q; }
    __syncthreads();

    // ---- redundant cross-warp scan in EVERY warp (no 2nd barrier) ----
    float p = (lane < NW) ? sWP[lane] : 1.0f;
    float q = (lane < NW) ? sWQ[lane] : 0.0f;
    #pragma unroll
    for (int off = 1; off < NW; off <<= 1) {
        float pu = __shfl_up_sync(0xFFFFFFFFu, p, off);
        float qu = __shfl_up_sync(0xFFFFFFFFu, q, off);
        if (lane >= off) { q = fmaf(p, qu, q); p *= pu; }
    }
    // block-start gamma = 0, so warp-start gamma = inclusive Q at wid-1.
    float gw = (wid == 0) ? 0.0f : __shfl_sync(0xFFFFFFFFu, q, wid - 1);
    float gt = fmaf(LPe, gw, LQe);      // thread-start gamma

    // ---- fixup (independent FMAs) + coalesced float4 stores ----
    float4* __restrict__ po = reinterpret_cast<float4*>(out + base);
    #pragma unroll
    for (int v = 0; v < 4; v++) {
        float4 o;
        o.x = fmaf(-dd[v*4+0], gt, ee[v*4+0]);
        o.y = fmaf(-dd[v*4+1], gt, ee[v*4+1]);
        o.z = fmaf(-dd[v*4+2], gt, ee[v*4+2]);
        o.w = fmaf(-dd[v*4+3], gt, ee[v*4+3]);
        po[v] = o;
    }
}

extern "C" void kernel_launch(void* const* d_in, const int* in_sizes, int n_in,
                              void* d_out, int out_size) {
    const float* eps = (const float*)d_in[0];
    const float* dt  = (const float*)d_in[1];
    float* out = (float*)d_out;

    maxwell_row_kernel<<<Bn, TPB>>>(eps, dt, out);
}